// round 16
// baseline (speedup 1.0000x reference)
#include <cuda_runtime.h>

typedef unsigned long long ULL;

// ---------------- packed f32x2 helpers (sm_103a FFMA2 path) ----------------
__device__ __forceinline__ ULL pk2(float lo, float hi) {
    ULL r; asm("mov.b64 %0, {%1,%2};" : "=l"(r) : "f"(lo), "f"(hi)); return r;
}
__device__ __forceinline__ void upk2(ULL v, float& lo, float& hi) {
    asm("mov.b64 {%0,%1}, %2;" : "=f"(lo), "=f"(hi) : "l"(v));
}
__device__ __forceinline__ ULL fma2(ULL a, ULL b, ULL c) {
    ULL d; asm("fma.rn.f32x2 %0, %1, %2, %3;" : "=l"(d) : "l"(a), "l"(b), "l"(c)); return d;
}
__device__ __forceinline__ ULL add2(ULL a, ULL b) {
    ULL d; asm("add.rn.f32x2 %0, %1, %2;" : "=l"(d) : "l"(a), "l"(b)); return d;
}
__device__ __forceinline__ float rsqrt_approx(float x) {
    float r; asm("rsqrt.approx.f32 %0, %1;" : "=f"(r) : "f"(x)); return r;
}

// ---------------- problem constants ----------------
constexpr int K    = 32;       // experts
constexpr int DI   = 10;       // input size
constexpr int DH   = 20;       // hidden size
constexpr int NHP  = DH / 2;   // hidden pairs = 10
constexpr int B    = 262144;
constexpr int THREADS = 128;
constexpr int R    = 4;        // batch rows per thread
constexpr int SPLIT = 4;       // expert splits across gridDim.y
constexpr int KPC  = K / SPLIT;    // experts per CTA = 8
constexpr int NKPC = KPC / 2;      // expert pairs per CTA = 4
constexpr int GRIDX = B / (R * THREADS);   // 512

// per-split partials: float4 j covers rows 2j,2j+1 as (n0,d0,n1,d1)
__device__ float4 g_part[SPLIT][B / 2];

// shared layout in ULL units (per CTA: 8 experts)
constexpr int U_W1 = 0;                       // [kl][hp][i] (h,h+1) pairs : 800 ULL
constexpr int U_BW = U_W1 + KPC * NHP * DI;   // [kl][hp]{(b1,b1'),(w2,w2')} : 160 ULL
constexpr int U_PV = U_BW + KPC * NHP * 2;    // [kpl][i] (-2p_k, -2p_k') : 40 ULL
constexpr int U_C2 = U_PV + NKPC * DI;        // [kpl] (|p_k|^2, |p_k'|^2) : 4 ULL
constexpr int U_B2 = U_C2 + NKPC;             // [kl] (b2, 0) : 8 ULL
constexpr int U_END = U_B2 + KPC;             // 1012 ULL
constexpr int SM_FLOATS = U_END * 2;          // ~8.1 KB

// minBlocksPerMultiprocessor=5 RAISES the reg allowance to the 5-CTA boundary
// (~102 regs vs ptxas's natural 91) so more LDS can be hoisted into the fma2
// shadow. Occupancy is unchanged: 5 CTAs / 20 warps per SM either way.
__global__ void __launch_bounds__(THREADS, 5)
piecewise_mlp_main(const float* __restrict__ in,
                   const float* __restrict__ W1,
                   const float* __restrict__ b1,
                   const float* __restrict__ W2,
                   const float* __restrict__ b2,
                   const float* __restrict__ proto)
{
    extern __shared__ float sm[];
    ULL* smU = (ULL*)sm;
    const int split = blockIdx.y;
    const int kbase = split * KPC;

    // ---- stage this split's 8 experts ----
    for (int idx = threadIdx.x; idx < KPC * NHP * DI; idx += THREADS) {
        int kl = idx / (NHP * DI), rem = idx % (NHP * DI);
        int hp = rem / DI, i = rem % DI;
        int k = kbase + kl;
        smU[U_W1 + idx] = pk2(W1[(k * DH + 2 * hp) * DI + i],
                              W1[(k * DH + 2 * hp + 1) * DI + i]);
    }
    for (int idx = threadIdx.x; idx < KPC * NHP * 2; idx += THREADS) {
        int kl = idx / (NHP * 2), rem = idx % (NHP * 2);
        int hp = rem / 2, w = rem % 2;
        int k = kbase + kl;
        const float* src = (w == 0) ? b1 : W2;   // W2 is [K,1,DH] flat
        smU[U_BW + idx] = pk2(src[k * DH + 2 * hp], src[k * DH + 2 * hp + 1]);
    }
    for (int idx = threadIdx.x; idx < NKPC * DI; idx += THREADS) {
        int kpl = idx / DI, i = idx % DI;
        int k = kbase + 2 * kpl;
        smU[U_PV + idx] = pk2(-2.0f * proto[k * DI + i],
                              -2.0f * proto[(k + 1) * DI + i]);
    }
    if (threadIdx.x < NKPC) {
        int k = kbase + 2 * threadIdx.x;
        float s0 = 0.0f, s1 = 0.0f;
        #pragma unroll
        for (int i = 0; i < DI; i++) {
            float a = proto[k * DI + i];
            float c = proto[(k + 1) * DI + i];
            s0 = fmaf(a, a, s0);
            s1 = fmaf(c, c, s1);
        }
        smU[U_C2 + threadIdx.x] = pk2(s0, s1);
    }
    if (threadIdx.x < KPC)
        smU[U_B2 + threadIdx.x] = pk2(b2[kbase + threadIdx.x], 0.0f);
    __syncthreads();

    // ---- load R=4 batch rows (160B contiguous), build dup packs (x,x) ----
    const int gt = blockIdx.x * THREADS + threadIdx.x;
    const float4* q = (const float4*)(in + (size_t)gt * R * DI);
    ULL x2[R][DI];
    #pragma unroll
    for (int v = 0; v < R * DI / 4; v++) {     // 10 float4 loads
        float4 f = q[v];
        int b0 = v * 4;
        x2[(b0 + 0) / DI][(b0 + 0) % DI] = pk2(f.x, f.x);
        x2[(b0 + 1) / DI][(b0 + 1) % DI] = pk2(f.y, f.y);
        x2[(b0 + 2) / DI][(b0 + 2) % DI] = pk2(f.z, f.z);
        x2[(b0 + 3) / DI][(b0 + 3) % DI] = pk2(f.w, f.w);
    }

    // |x|^2 as dup packs, once per row
    ULL xxp[R];
    #pragma unroll
    for (int r = 0; r < R; r++) {
        ULL acc = 0ull;
        #pragma unroll
        for (int i = 0; i < DI; i++) acc = fma2(x2[r][i], x2[r][i], acc);
        xxp[r] = acc;
    }

    ULL num2[R], den2[R];
    #pragma unroll
    for (int r = 0; r < R; r++) { num2[r] = 0ull; den2[r] = 0ull; }

    const ULL* w1p = smU + U_W1;
    const ULL* bwp = smU + U_BW;
    const ULL* pvp = smU + U_PV;
    const ULL* c2p = smU + U_C2;
    const ULL* b2p = smU + U_B2;

    #pragma unroll 1
    for (int kp = 0; kp < NKPC; kp++) {
        // ---- gating: d2 = |p|^2 + |x|^2 + sum_i (-2 p_i) x_i, packed per expert pair ----
        const ulonglong2* pq = (const ulonglong2*)(pvp + kp * DI);
        ulonglong2 p0 = pq[0], p1 = pq[1], p2 = pq[2], p3 = pq[3], p4 = pq[4];
        ULL c2u = c2p[kp];
        ULL e2[R];
        #pragma unroll
        for (int r = 0; r < R; r++) {
            ULL d2 = add2(c2u, xxp[r]);
            d2 = fma2(x2[r][0], p0.x, d2);
            d2 = fma2(x2[r][1], p0.y, d2);
            d2 = fma2(x2[r][2], p1.x, d2);
            d2 = fma2(x2[r][3], p1.y, d2);
            d2 = fma2(x2[r][4], p2.x, d2);
            d2 = fma2(x2[r][5], p2.y, d2);
            d2 = fma2(x2[r][6], p3.x, d2);
            d2 = fma2(x2[r][7], p3.y, d2);
            d2 = fma2(x2[r][8], p4.x, d2);
            d2 = fma2(x2[r][9], p4.y, d2);
            float da, db; upk2(d2, da, db);
            da = fmaxf(da, 1e-12f);
            db = fmaxf(db, 1e-12f);
            float ea = __expf(-da * rsqrt_approx(da));
            float eb = __expf(-db * rsqrt_approx(db));
            e2[r] = pk2(ea, eb);
            den2[r] = add2(den2[r], e2[r]);
        }

        // ---- MLPs for the two experts of this pair ----
        float predk[2][R];
        #pragma unroll
        for (int sub = 0; sub < 2; sub++) {
            int kl = 2 * kp + sub;
            ULL b2u = b2p[kl];                 // (b2, 0)
            ULL pred2[R];
            #pragma unroll
            for (int r = 0; r < R; r++) pred2[r] = b2u;

            #pragma unroll
            for (int hp = 0; hp < NHP; hp++) {
                const ulonglong2* wrow = (const ulonglong2*)(w1p + (kl * NHP + hp) * DI);
                ulonglong2 w0 = wrow[0], w1v = wrow[1], w2v = wrow[2], w3 = wrow[3], w4 = wrow[4];
                ulonglong2 bwv = ((const ulonglong2*)bwp)[kl * NHP + hp]; // (b1pair, w2pair)
                #pragma unroll
                for (int r = 0; r < R; r++) {
                    ULL acc = bwv.x;
                    acc = fma2(x2[r][0], w0.x,  acc);
                    acc = fma2(x2[r][1], w0.y,  acc);
                    acc = fma2(x2[r][2], w1v.x, acc);
                    acc = fma2(x2[r][3], w1v.y, acc);
                    acc = fma2(x2[r][4], w2v.x, acc);
                    acc = fma2(x2[r][5], w2v.y, acc);
                    acc = fma2(x2[r][6], w3.x,  acc);
                    acc = fma2(x2[r][7], w3.y,  acc);
                    acc = fma2(x2[r][8], w4.x,  acc);
                    acc = fma2(x2[r][9], w4.y,  acc);
                    float hl, hh; upk2(acc, hl, hh);
                    hl = fmaxf(hl, 0.0f);
                    hh = fmaxf(hh, 0.0f);
                    pred2[r] = fma2(pk2(hl, hh), bwv.y, pred2[r]);
                }
            }
            #pragma unroll
            for (int r = 0; r < R; r++) {
                float pl, ph; upk2(pred2[r], pl, ph);
                predk[sub][r] = pl + ph;       // b2 folded into init
            }
        }

        // ---- packed num accumulation: (pred_k, pred_k+1) * (e_k, e_k+1) ----
        #pragma unroll
        for (int r = 0; r < R; r++)
            num2[r] = fma2(pk2(predk[0][r], predk[1][r]), e2[r], num2[r]);
    }

    // ---- write partial (num, den) per row for this split ----
    float n[R], d[R];
    #pragma unroll
    for (int r = 0; r < R; r++) {
        float nl, nh, dl, dh;
        upk2(num2[r], nl, nh); upk2(den2[r], dl, dh);
        n[r] = nl + nh;
        d[r] = dl + dh;
    }
    float4* dst = &g_part[split][(size_t)gt * 2];
    dst[0] = make_float4(n[0], d[0], n[1], d[1]);
    dst[1] = make_float4(n[2], d[2], n[3], d[3]);
}

// ---- combine: 2 rows per thread via float4 loads (8 independent LDGs) ----
constexpr int CTHREADS = 256;
constexpr int CGRID = B / (2 * CTHREADS);   // 512

__global__ void __launch_bounds__(CTHREADS)
piecewise_mlp_combine(float* __restrict__ out)
{
    const int t = blockIdx.x * CTHREADS + threadIdx.x;   // 2-row group index
    float n0 = 0.0f, d0 = 0.0f, n1 = 0.0f, d1 = 0.0f;
    #pragma unroll
    for (int s = 0; s < SPLIT; s++) {
        float4 v = g_part[s][t];             // (n0,d0,n1,d1) for rows 2t,2t+1
        n0 += v.x; d0 += v.y;
        n1 += v.z; d1 += v.w;
    }
    float2 o;
    o.x = __fdividef(n0, d0);
    o.y = __fdividef(n1, d1);
    ((float2*)out)[t] = o;
}

extern "C" void kernel_launch(void* const* d_in, const int* in_sizes, int n_in,
                              void* d_out, int out_size)
{
    const float* in    = (const float*)d_in[0];
    const float* W1    = (const float*)d_in[1];
    const float* b1    = (const float*)d_in[2];
    const float* W2    = (const float*)d_in[3];
    const float* b2    = (const float*)d_in[4];
    const float* proto = (const float*)d_in[5];
    float* out = (float*)d_out;

    dim3 grid(GRIDX, SPLIT);
    piecewise_mlp_main<<<grid, THREADS, SM_FLOATS * sizeof(float)>>>(
        in, W1, b1, W2, b2, proto);
    piecewise_mlp_combine<<<CGRID, CTHREADS>>>(out);
}

// round 17
// speedup vs baseline: 1.1602x; 1.1602x over previous
#include <cuda_runtime.h>

typedef unsigned long long ULL;

// ---------------- packed f32x2 helpers (sm_103a FFMA2 path) ----------------
__device__ __forceinline__ ULL pk2(float lo, float hi) {
    ULL r; asm("mov.b64 %0, {%1,%2};" : "=l"(r) : "f"(lo), "f"(hi)); return r;
}
__device__ __forceinline__ void upk2(ULL v, float& lo, float& hi) {
    asm("mov.b64 {%0,%1}, %2;" : "=f"(lo), "=f"(hi) : "l"(v));
}
__device__ __forceinline__ ULL fma2(ULL a, ULL b, ULL c) {
    ULL d; asm("fma.rn.f32x2 %0, %1, %2, %3;" : "=l"(d) : "l"(a), "l"(b), "l"(c)); return d;
}
__device__ __forceinline__ ULL add2(ULL a, ULL b) {
    ULL d; asm("add.rn.f32x2 %0, %1, %2;" : "=l"(d) : "l"(a), "l"(b)); return d;
}
__device__ __forceinline__ float rsqrt_approx(float x) {
    float r; asm("rsqrt.approx.f32 %0, %1;" : "=f"(r) : "f"(x)); return r;
}

// ---------------- problem constants ----------------
constexpr int K    = 32;       // experts
constexpr int DI   = 10;       // input size
constexpr int DH   = 20;       // hidden size
constexpr int NHP  = DH / 2;   // hidden pairs = 10
constexpr int B    = 262144;
constexpr int THREADS = 128;
constexpr int R    = 4;        // batch rows per thread
constexpr int SPLIT = 4;       // expert splits across gridDim.y
constexpr int KPC  = K / SPLIT;    // experts per CTA = 8
constexpr int NKPC = KPC / 2;      // expert pairs per CTA = 4
constexpr int GRIDX = B / (R * THREADS);   // 512

// per-split partials: float4 j covers rows 2j,2j+1 as (n0,d0,n1,d1)
__device__ float4 g_part[SPLIT][B / 2];

// shared layout in ULL units (per CTA: 8 experts)
constexpr int U_W1 = 0;                       // [kl][hp][i] (h,h+1) pairs : 800 ULL
constexpr int U_BW = U_W1 + KPC * NHP * DI;   // [kl][hp]{(b1,b1'),(w2,w2')} : 160 ULL
constexpr int U_PV = U_BW + KPC * NHP * 2;    // [kpl][i] (-2p_k, -2p_k') : 40 ULL
constexpr int U_C2 = U_PV + NKPC * DI;        // [kpl] (|p_k|^2, |p_k'|^2) : 4 ULL
constexpr int U_B2 = U_C2 + NKPC;             // [kl] (b2, 0) : 8 ULL
constexpr int U_END = U_B2 + KPC;             // 1012 ULL
constexpr int SM_FLOATS = U_END * 2;          // ~8.1 KB

// Natural register allocation (91 regs, 5 CTAs/SM) — every launch_bounds
// second-arg annotation (R7/R9/R10/R16) regressed this kernel.
__global__ void __launch_bounds__(THREADS)
piecewise_mlp_main(const float* __restrict__ in,
                   const float* __restrict__ W1,
                   const float* __restrict__ b1,
                   const float* __restrict__ W2,
                   const float* __restrict__ b2,
                   const float* __restrict__ proto)
{
    extern __shared__ float sm[];
    ULL* smU = (ULL*)sm;
    const int split = blockIdx.y;
    const int kbase = split * KPC;

    // ---- stage this split's 8 experts ----
    for (int idx = threadIdx.x; idx < KPC * NHP * DI; idx += THREADS) {
        int kl = idx / (NHP * DI), rem = idx % (NHP * DI);
        int hp = rem / DI, i = rem % DI;
        int k = kbase + kl;
        smU[U_W1 + idx] = pk2(W1[(k * DH + 2 * hp) * DI + i],
                              W1[(k * DH + 2 * hp + 1) * DI + i]);
    }
    for (int idx = threadIdx.x; idx < KPC * NHP * 2; idx += THREADS) {
        int kl = idx / (NHP * 2), rem = idx % (NHP * 2);
        int hp = rem / 2, w = rem % 2;
        int k = kbase + kl;
        const float* src = (w == 0) ? b1 : W2;   // W2 is [K,1,DH] flat
        smU[U_BW + idx] = pk2(src[k * DH + 2 * hp], src[k * DH + 2 * hp + 1]);
    }
    for (int idx = threadIdx.x; idx < NKPC * DI; idx += THREADS) {
        int kpl = idx / DI, i = idx % DI;
        int k = kbase + 2 * kpl;
        smU[U_PV + idx] = pk2(-2.0f * proto[k * DI + i],
                              -2.0f * proto[(k + 1) * DI + i]);
    }
    if (threadIdx.x < NKPC) {
        int k = kbase + 2 * threadIdx.x;
        float s0 = 0.0f, s1 = 0.0f;
        #pragma unroll
        for (int i = 0; i < DI; i++) {
            float a = proto[k * DI + i];
            float c = proto[(k + 1) * DI + i];
            s0 = fmaf(a, a, s0);
            s1 = fmaf(c, c, s1);
        }
        smU[U_C2 + threadIdx.x] = pk2(s0, s1);
    }
    if (threadIdx.x < KPC)
        smU[U_B2 + threadIdx.x] = pk2(b2[kbase + threadIdx.x], 0.0f);
    __syncthreads();

    // ---- load R=4 batch rows (160B contiguous), build dup packs (x,x) ----
    const int gt = blockIdx.x * THREADS + threadIdx.x;
    const float4* q = (const float4*)(in + (size_t)gt * R * DI);
    ULL x2[R][DI];
    #pragma unroll
    for (int v = 0; v < R * DI / 4; v++) {     // 10 float4 loads
        float4 f = q[v];
        int b0 = v * 4;
        x2[(b0 + 0) / DI][(b0 + 0) % DI] = pk2(f.x, f.x);
        x2[(b0 + 1) / DI][(b0 + 1) % DI] = pk2(f.y, f.y);
        x2[(b0 + 2) / DI][(b0 + 2) % DI] = pk2(f.z, f.z);
        x2[(b0 + 3) / DI][(b0 + 3) % DI] = pk2(f.w, f.w);
    }

    // |x|^2 as dup packs, once per row
    ULL xxp[R];
    #pragma unroll
    for (int r = 0; r < R; r++) {
        ULL acc = 0ull;
        #pragma unroll
        for (int i = 0; i < DI; i++) acc = fma2(x2[r][i], x2[r][i], acc);
        xxp[r] = acc;
    }

    ULL num2[R], den2[R];
    #pragma unroll
    for (int r = 0; r < R; r++) { num2[r] = 0ull; den2[r] = 0ull; }

    const ULL* w1p = smU + U_W1;
    const ULL* bwp = smU + U_BW;
    const ULL* pvp = smU + U_PV;
    const ULL* c2p = smU + U_C2;
    const ULL* b2p = smU + U_B2;

    #pragma unroll 1
    for (int kp = 0; kp < NKPC; kp++) {
        // ---- gating: d2 = |p|^2 + |x|^2 + sum_i (-2 p_i) x_i, packed per expert pair ----
        const ulonglong2* pq = (const ulonglong2*)(pvp + kp * DI);
        ulonglong2 p0 = pq[0], p1 = pq[1], p2 = pq[2], p3 = pq[3], p4 = pq[4];
        ULL c2u = c2p[kp];
        ULL e2[R];
        #pragma unroll
        for (int r = 0; r < R; r++) {
            ULL d2 = add2(c2u, xxp[r]);
            d2 = fma2(x2[r][0], p0.x, d2);
            d2 = fma2(x2[r][1], p0.y, d2);
            d2 = fma2(x2[r][2], p1.x, d2);
            d2 = fma2(x2[r][3], p1.y, d2);
            d2 = fma2(x2[r][4], p2.x, d2);
            d2 = fma2(x2[r][5], p2.y, d2);
            d2 = fma2(x2[r][6], p3.x, d2);
            d2 = fma2(x2[r][7], p3.y, d2);
            d2 = fma2(x2[r][8], p4.x, d2);
            d2 = fma2(x2[r][9], p4.y, d2);
            float da, db; upk2(d2, da, db);
            da = fmaxf(da, 1e-12f);
            db = fmaxf(db, 1e-12f);
            float ea = __expf(-da * rsqrt_approx(da));
            float eb = __expf(-db * rsqrt_approx(db));
            e2[r] = pk2(ea, eb);
            den2[r] = add2(den2[r], e2[r]);
        }

        // ---- MLPs for the two experts of this pair ----
        float predk[2][R];
        #pragma unroll
        for (int sub = 0; sub < 2; sub++) {
            int kl = 2 * kp + sub;
            ULL b2u = b2p[kl];                 // (b2, 0)
            ULL pred2[R];
            #pragma unroll
            for (int r = 0; r < R; r++) pred2[r] = b2u;

            #pragma unroll
            for (int hp = 0; hp < NHP; hp++) {
                const ulonglong2* wrow = (const ulonglong2*)(w1p + (kl * NHP + hp) * DI);
                ulonglong2 w0 = wrow[0], w1v = wrow[1], w2v = wrow[2], w3 = wrow[3], w4 = wrow[4];
                ulonglong2 bwv = ((const ulonglong2*)bwp)[kl * NHP + hp]; // (b1pair, w2pair)
                #pragma unroll
                for (int r = 0; r < R; r++) {
                    ULL acc = bwv.x;
                    acc = fma2(x2[r][0], w0.x,  acc);
                    acc = fma2(x2[r][1], w0.y,  acc);
                    acc = fma2(x2[r][2], w1v.x, acc);
                    acc = fma2(x2[r][3], w1v.y, acc);
                    acc = fma2(x2[r][4], w2v.x, acc);
                    acc = fma2(x2[r][5], w2v.y, acc);
                    acc = fma2(x2[r][6], w3.x,  acc);
                    acc = fma2(x2[r][7], w3.y,  acc);
                    acc = fma2(x2[r][8], w4.x,  acc);
                    acc = fma2(x2[r][9], w4.y,  acc);
                    float hl, hh; upk2(acc, hl, hh);
                    hl = fmaxf(hl, 0.0f);
                    hh = fmaxf(hh, 0.0f);
                    pred2[r] = fma2(pk2(hl, hh), bwv.y, pred2[r]);
                }
            }
            #pragma unroll
            for (int r = 0; r < R; r++) {
                float pl, ph; upk2(pred2[r], pl, ph);
                predk[sub][r] = pl + ph;       // b2 folded into init
            }
        }

        // ---- packed num accumulation: (pred_k, pred_k+1) * (e_k, e_k+1) ----
        #pragma unroll
        for (int r = 0; r < R; r++)
            num2[r] = fma2(pk2(predk[0][r], predk[1][r]), e2[r], num2[r]);
    }

    // ---- write partial (num, den) per row for this split ----
    float n[R], d[R];
    #pragma unroll
    for (int r = 0; r < R; r++) {
        float nl, nh, dl, dh;
        upk2(num2[r], nl, nh); upk2(den2[r], dl, dh);
        n[r] = nl + nh;
        d[r] = dl + dh;
    }
    float4* dst = &g_part[split][(size_t)gt * 2];
    dst[0] = make_float4(n[0], d[0], n[1], d[1]);
    dst[1] = make_float4(n[2], d[2], n[3], d[3]);
}

// ---- combine: 2 rows per thread via float4 loads (8 independent LDGs) ----
constexpr int CTHREADS = 256;
constexpr int CGRID = B / (2 * CTHREADS);   // 512

__global__ void __launch_bounds__(CTHREADS)
piecewise_mlp_combine(float* __restrict__ out)
{
    const int t = blockIdx.x * CTHREADS + threadIdx.x;   // 2-row group index
    float n0 = 0.0f, d0 = 0.0f, n1 = 0.0f, d1 = 0.0f;
    #pragma unroll
    for (int s = 0; s < SPLIT; s++) {
        float4 v = g_part[s][t];             // (n0,d0,n1,d1) for rows 2t,2t+1
        n0 += v.x; d0 += v.y;
        n1 += v.z; d1 += v.w;
    }
    float2 o;
    o.x = __fdividef(n0, d0);
    o.y = __fdividef(n1, d1);
    ((float2*)out)[t] = o;
}

extern "C" void kernel_launch(void* const* d_in, const int* in_sizes, int n_in,
                              void* d_out, int out_size)
{
    const float* in    = (const float*)d_in[0];
    const float* W1    = (const float*)d_in[1];
    const float* b1    = (const float*)d_in[2];
    const float* W2    = (const float*)d_in[3];
    const float* b2    = (const float*)d_in[4];
    const float* proto = (const float*)d_in[5];
    float* out = (float*)d_out;

    dim3 grid(GRIDX, SPLIT);
    piecewise_mlp_main<<<grid, THREADS, SM_FLOATS * sizeof(float)>>>(
        in, W1, b1, W2, b2, proto);
    piecewise_mlp_combine<<<CGRID, CTHREADS>>>(out);
}